// round 15
// baseline (speedup 1.0000x reference)
#include <cuda_runtime.h>
#include <math.h>

#define BB   8
#define NS   25
#define NQ   75
#define WAY  5
#define CCH  512
#define HW   36
#define MID  6
#define NCLS 64
#define PAIRS (BB*WAY*NQ)   /* 3000 */
#define CHW  (CCH*HW)       /* 18432 */
#define CHW4 (CHW/4)        /* 4608 */
#define NTOT (BB*NQ*HW)     /* 21600 */

// ---------------- scratch ----------------
__device__ float g_protos[BB*WAY*CHW];     // [b,i,c,x]
__device__ float g_rn1 [BB*WAY*HW];
__device__ float g_mw1 [BB*WAY*CCH];
__device__ float g_rn2 [BB*NQ*HW];
__device__ float g_mw2 [BB*NQ*CCH];
__device__ float g_yv  [2*PAIRS*MID];
__device__ float g_stats[24];
__device__ float g_wv1 [PAIRS*HW];
__device__ float g_v1  [PAIRS*CCH];        // v1, later NORMALIZED pooled
__device__ float g_v2  [PAIRS*CCH];
__device__ float g_asel[BB*NQ*HW];

// prototypes (float4) + zero stats
__global__ void __launch_bounds__(288) k_protos(const float* __restrict__ sup,
                                                const float* __restrict__ st) {
    int b = blockIdx.y, t = threadIdx.x;
    if (blockIdx.x == 0 && b == 0 && t < 24) g_stats[t] = 0.f;
    __shared__ float sts[NS*WAY];
    __shared__ float rcnt[WAY];
    if (t < NS*WAY) sts[t] = st[b*NS*WAY + t];
    __syncthreads();
    if (t < WAY) { float s = 0.f; for (int n = 0; n < NS; n++) s += sts[n*WAY + t]; rcnt[t] = 1.f/s; }
    __syncthreads();
    int d4 = blockIdx.x*288 + t;
    const float4* sb = (const float4*)sup + (size_t)b*NS*CHW4 + d4;
    float4 acc[WAY];
    #pragma unroll
    for (int w = 0; w < WAY; w++) acc[w] = make_float4(0.f,0.f,0.f,0.f);
    for (int n = 0; n < NS; n++) {
        float4 v = sb[(size_t)n*CHW4];
        #pragma unroll
        for (int w = 0; w < WAY; w++) {
            float s = sts[n*WAY + w];
            acc[w].x += s*v.x; acc[w].y += s*v.y; acc[w].z += s*v.z; acc[w].w += s*v.w;
        }
    }
    #pragma unroll
    for (int w = 0; w < WAY; w++) {
        float r = rcnt[w];
        float4 o = make_float4(acc[w].x*r, acc[w].y*r, acc[w].z*r, acc[w].w*r);
        ((float4*)g_protos)[(size_t)(b*WAY + w)*CHW4 + d4] = o;
    }
}

// per (b,i): rn1, mw1
__global__ void __launch_bounds__(288) k_prep1() {
    int bi = blockIdx.x, t = threadIdx.x;
    const float4* P4 = (const float4*)(g_protos + (size_t)bi*CHW);
    __shared__ float part[288*4];
    __shared__ float rn1s[HW];
    float s0=0.f,s1=0.f,s2=0.f,s3=0.f;
    #pragma unroll 4
    for (int k = 0; k < 16; k++) {
        float4 v = P4[t + 288*k];
        s0 += v.x*v.x; s1 += v.y*v.y; s2 += v.z*v.z; s3 += v.w*v.w;
    }
    part[4*t]=s0; part[4*t+1]=s1; part[4*t+2]=s2; part[4*t+3]=s3;
    __syncthreads();
    if (t < HW) {
        int y4 = t >> 2, j = t & 3;
        float s = 0.f;
        #pragma unroll
        for (int m = 0; m < 32; m++) s += part[4*(y4 + 9*m) + j];
        float r = 1.f/fmaxf(sqrtf(s), 1e-12f);
        rn1s[t] = r; g_rn1[bi*HW + t] = r;
    }
    __syncthreads();
    for (int c = t; c < CCH; c += 288) {
        const float4* row = P4 + c*9;
        float a = 0.f;
        #pragma unroll
        for (int y4 = 0; y4 < 9; y4++) {
            float4 v = row[y4];
            a += v.x*rn1s[y4*4] + v.y*rn1s[y4*4+1] + v.z*rn1s[y4*4+2] + v.w*rn1s[y4*4+3];
        }
        g_mw1[bi*CCH + c] = a*(1.f/36.f);
    }
}

// fused prep2 + ch1(path1 conv1); per bq; writes rn2, mw2
__global__ void __launch_bounds__(288) k_prep2ch1(const float* __restrict__ Q,
                                                  const float* __restrict__ w1,
                                                  const float* __restrict__ b1) {
    int bq = blockIdx.x; int b = bq/NQ, q = bq%NQ;
    int t = threadIdx.x;
    __shared__ float mw1s[WAY*CCH];
    __shared__ float redA[20][288];
    __shared__ float part[288*4];
    __shared__ float rn2s[HW];
    __shared__ float ch1s[WAY][HW];
    {
        const float4* src = (const float4*)(g_mw1 + b*WAY*CCH);
        float4* dst = (float4*)mw1s;
        for (int i4 = t; i4 < WAY*CCH/4; i4 += 288) dst[i4] = src[i4];
    }
    __syncthreads();
    const float4* Q4 = (const float4*)(Q + (size_t)bq*CHW);
    float aacc[WAY][4];
    float sq[4] = {0.f,0.f,0.f,0.f};
    #pragma unroll
    for (int i = 0; i < WAY; i++)
        #pragma unroll
        for (int j = 0; j < 4; j++) aacc[i][j] = 0.f;
    #pragma unroll 4
    for (int k = 0; k < 16; k++) {
        int idx = t + 288*k;
        int c = idx/9;
        float4 v = Q4[idx];
        sq[0] += v.x*v.x; sq[1] += v.y*v.y; sq[2] += v.z*v.z; sq[3] += v.w*v.w;
        #pragma unroll
        for (int i = 0; i < WAY; i++) {
            float w = mw1s[i*CCH + c];
            aacc[i][0] += w*v.x; aacc[i][1] += w*v.y; aacc[i][2] += w*v.z; aacc[i][3] += w*v.w;
        }
    }
    #pragma unroll
    for (int j = 0; j < 4; j++) part[4*t + j] = sq[j];
    #pragma unroll
    for (int i = 0; i < WAY; i++)
        #pragma unroll
        for (int j = 0; j < 4; j++) redA[i*4 + j][t] = aacc[i][j];
    __syncthreads();
    if (t < HW) {
        int y4 = t >> 2, j = t & 3;
        float s = 0.f;
        #pragma unroll
        for (int m = 0; m < 32; m++) s += part[4*(y4 + 9*m) + j];
        float r = 1.f/fmaxf(sqrtf(s), 1e-12f);
        rn2s[t] = r; g_rn2[bq*HW + t] = r;
    }
    __syncthreads();
    if (t < WAY*HW) {
        int i = t/HW, y = t%HW;
        int y4 = y >> 2, j = y & 3;
        float s = 0.f;
        #pragma unroll
        for (int m = 0; m < 32; m++) s += redA[i*4 + j][y4 + 9*m];
        ch1s[i][y] = s*rn2s[y];
    }
    // pass2: mw2 (Q rows L1-resident)
    for (int c = t; c < CCH; c += 288) {
        const float4* row = Q4 + c*9;
        float a = 0.f;
        #pragma unroll
        for (int y4 = 0; y4 < 9; y4++) {
            float4 v = row[y4];
            a += v.x*rn2s[y4*4] + v.y*rn2s[y4*4+1] + v.z*rn2s[y4*4+2] + v.w*rn2s[y4*4+3];
        }
        g_mw2[bq*CCH + c] = a*(1.f/36.f);
    }
    __syncthreads();
    if (t < WAY*MID) {  // path1 conv1
        int i = t/MID, m = t%MID;
        float a = b1[m];
        #pragma unroll
        for (int y = 0; y < HW; y++) a += w1[m*HW + y]*ch1s[i][y];
        int p = (b*WAY + i)*NQ + q;
        g_yv[p*MID + m] = a;
        atomicAdd(&g_stats[m], a); atomicAdd(&g_stats[MID + m], a*a);
    }
}

// path2 conv input + conv1 + BN stats; per (bi, q-chunk16); smem-tiled P (c-chunk 64)
// 576 threads: exactly one (q,x) output per thread; same math order as round 6
__global__ void __launch_bounds__(576) k_ch2f(const float* __restrict__ w1,
                                              const float* __restrict__ b1) {
    int bi = blockIdx.x; int qc = blockIdx.y*16;
    int b = bi/WAY;
    const float* P = g_protos + (size_t)bi*CHW;
    __shared__ float mw2s[16*CCH];   // 32KB
    __shared__ float tile[64*37];    // 9.47KB
    __shared__ float ch2s[16][HW];
    __shared__ float rn1s[HW];
    int t = threadIdx.x;
    if (t < HW) rn1s[t] = g_rn1[bi*HW + t];
    {
        float4* dst = (float4*)mw2s;
        const float4* src = (const float4*)g_mw2;
        for (int i4 = t; i4 < 16*128; i4 += 576) {
            int ql = i4 >> 7; int qq = qc + ql;
            dst[i4] = (qq < NQ) ? src[(size_t)(b*NQ + qq)*128 + (i4 & 127)]
                                : make_float4(0.f,0.f,0.f,0.f);
        }
    }
    __syncthreads();
    int q0 = t/36, x0 = t%36;          // one (q0,x0) per thread (16*36 = 576)
    float acc0 = 0.f;
    for (int c0 = 0; c0 < CCH; c0 += 64) {
        for (int idx = t; idx < 64*36; idx += 576) {
            int r = idx/36, xx = idx%36;
            tile[r*37 + xx] = P[(c0 + r)*HW + xx];
        }
        __syncthreads();
        #pragma unroll 8
        for (int c = 0; c < 64; c++) {
            float pv = tile[c*37 + x0];
            acc0 += mw2s[q0*CCH + c0 + c]*pv;
        }
        __syncthreads();
    }
    ch2s[q0][x0] = acc0*rn1s[x0];
    __syncthreads();
    if (t < 16*MID) {
        int g2 = t/MID, m = t%MID; int q2 = qc + g2;
        if (q2 < NQ) {
            float s = b1[m];
            #pragma unroll
            for (int xx = 0; xx < HW; xx++) s += w1[m*HW + xx]*ch2s[g2][xx];
            int p = bi*NQ + q2;
            g_yv[PAIRS*MID + p*MID + m] = s;
            atomicAdd(&g_stats[12 + m], s); atomicAdd(&g_stats[18 + m], s*s);
        }
    }
}

// fused BN-finalize + conv2 (aw) + v2 matvec; per (bi, q-chunk25); c-chunk 64
__global__ void __launch_bounds__(288) k_awv2(const float* __restrict__ gam,
                                              const float* __restrict__ bet,
                                              const float* __restrict__ w2,
                                              const float* __restrict__ b2) {
    int bi = blockIdx.x; int qc = blockIdx.y*25;
    int b = bi/WAY;
    int pb = bi*NQ + qc;
    const float* P = g_protos + (size_t)bi*CHW;
    __shared__ float bnps[24];
    __shared__ float hsh[25][12];
    __shared__ float wv2s[25*HW];
    __shared__ float tile[64*37];
    __shared__ float rn1s[HW];
    int t = threadIdx.x;
    if (t < 12) {
        int path = t/MID, m = t%MID;
        float sum = g_stats[path*12 + m];
        float sqs = g_stats[path*12 + MID + m];
        float mu  = sum/(float)PAIRS;
        float var = sqs/(float)PAIRS - mu*mu;
        bnps[path*12 + m]       = mu;
        bnps[path*12 + MID + m] = rsqrtf(var + 1e-5f);
    }
    if (t >= 64 && t < 64 + HW) rn1s[t - 64] = g_rn1[bi*HW + (t - 64)];
    __syncthreads();
    for (int idx = t; idx < 300; idx += 288) {   // cover all 25 pairs
        int pl = idx/12, tt = idx%12, path = tt/MID, m = tt%MID;
        int p = pb + pl;
        float v = g_yv[path*PAIRS*MID + p*MID + m];
        float z = gam[m]*(v - bnps[path*12 + m])*bnps[path*12 + MID + m] + bet[m];
        hsh[pl][tt] = fmaxf(z, 0.f);
    }
    __syncthreads();
    for (int idx = t; idx < 25*72; idx += 288) {
        int pl = idx/72, tt = idx%72, path = tt/HW, k = tt%HW;
        int p = pb + pl; int bq = b*NQ + qc + pl;
        float a = b2[k];
        #pragma unroll
        for (int m = 0; m < MID; m++) a += w2[k*MID + m]*hsh[pl][path*MID + m];
        if (path == 0) g_wv1[p*HW + k] = a * g_rn2[bq*HW + k];
        else           wv2s[pl*HW + k] = a * rn1s[k];
    }
    __syncthreads();
    // v2[p,c] = sum_x P[c,x]*wv2[p,x]
    for (int c0 = 0; c0 < CCH; c0 += 64) {
        for (int idx = t; idx < 64*36; idx += 288) {
            int r = idx/36, xx = idx%36;
            tile[r*37 + xx] = P[(c0 + r)*HW + xx];
        }
        __syncthreads();
        #pragma unroll
        for (int r = 0; r < 6; r++) {
            int item = t + 288*r;
            if (item < 1600) {
                int q = item >> 6, c_l = item & 63;
                float a = 0.f;
                #pragma unroll
                for (int xx = 0; xx < HW; xx++) a += tile[c_l*37 + xx]*wv2s[q*HW + xx];
                g_v2[(size_t)(pb + q)*CCH + c0 + c_l] = a;
            }
        }
        __syncthreads();
    }
}

// fused v1 + s2 + attsel; per bq, smem-tiled Q pass (c-chunk 64)
__global__ void __launch_bounds__(288) k_v1s2(const float* __restrict__ Q,
                                              const float* __restrict__ qt) {
    int bq = blockIdx.x; int b = bq/NQ, q = bq%NQ;
    int t = threadIdx.x;
    __shared__ float v2s[WAY*CCH];
    __shared__ float wv1s[WAY][HW];
    __shared__ float tile[64*37];
    __shared__ float rn2s[HW];
    __shared__ float s2s[WAY][HW];
    __shared__ float mx[WAY], sm[WAY], qts[WAY];
    {
        float4* dst = (float4*)v2s;
        for (int i4 = t; i4 < WAY*CCH/4; i4 += 288) {
            int i = i4/(CCH/4);
            const float4* src = (const float4*)(g_v2 + (size_t)((b*WAY + i)*NQ + q)*CCH);
            dst[i4] = src[i4 - i*(CCH/4)];
        }
    }
    if (t < WAY*HW) wv1s[t/HW][t%HW] = g_wv1[((b*WAY + t/HW)*NQ + q)*HW + t%HW];
    if (t < HW) rn2s[t] = g_rn2[bq*HW + t];
    if (t < WAY) qts[t] = qt[(size_t)bq*WAY + t];
    __syncthreads();
    const float* Qb = Q + (size_t)bq*CHW;
    int si = (t < 180) ? t/36 : 0;
    int sx = t%36;
    float s2a = 0.f;
    for (int c0 = 0; c0 < CCH; c0 += 64) {
        for (int idx = t; idx < 64*36; idx += 288) {
            int r = idx/36, xx = idx%36;
            tile[r*37 + xx] = Qb[(c0 + r)*HW + xx];
        }
        __syncthreads();
        #pragma unroll
        for (int r = 0; r < 2; r++) {
            int item = t + 288*r;
            if (item < 320) {
                int i = item >> 6, c_l = item & 63;
                float a = 0.f;
                #pragma unroll
                for (int y = 0; y < HW; y++) a += tile[c_l*37 + y]*wv1s[i][y];
                g_v1[(size_t)((b*WAY + i)*NQ + q)*CCH + c0 + c_l] = a;
            }
        }
        if (t < 180) {
            #pragma unroll 8
            for (int c = 0; c < 64; c++) s2a += v2s[si*CCH + c0 + c]*tile[c*37 + sx];
        }
        __syncthreads();
    }
    if (t < 180) s2s[si][sx] = s2a * rn2s[sx] * (1.f/36.f);
    __syncthreads();
    if (t < WAY) {
        float m = -1e30f;
        #pragma unroll
        for (int yy = 0; yy < HW; yy++) m = fmaxf(m, s2s[t][yy]);
        mx[t] = m;
    }
    __syncthreads();
    if (t < 180) s2s[si][sx] = expf((s2s[si][sx] - mx[si])*40.f);
    __syncthreads();
    if (t < WAY) {
        float s = 0.f;
        #pragma unroll
        for (int yy = 0; yy < HW; yy++) s += s2s[t][yy];
        sm[t] = s;
    }
    __syncthreads();
    if (t < HW) {
        float a = 0.f;
        #pragma unroll
        for (int i = 0; i < WAY; i++) a += (s2s[i][t]/sm[i] + 1.f)*qts[i];
        g_asel[bq*HW + t] = a;
    }
}

// fused s1 + softmax + proto-pool + l2norm; per (bi, q-chunk16)
__global__ void __launch_bounds__(288) k_s1pool() {
    int bi = blockIdx.x; int qc = blockIdx.y*16;
    const float* P = g_protos + (size_t)bi*CHW;
    __shared__ float v1s[16*CCH];
    __shared__ float tile[64*37];
    __shared__ float att[16][HW];
    __shared__ float rn1s[HW];
    __shared__ float mx[16], sm[16];
    __shared__ float pnfs[16];
    int t = threadIdx.x;
    if (t < HW) rn1s[t] = g_rn1[bi*HW + t];
    {
        float4* dst = (float4*)v1s;
        const float4* src = (const float4*)g_v1;
        for (int i4 = t; i4 < 16*CCH/4; i4 += 288) {
            int ql = i4 >> 7;
            int qq = qc + ql;
            dst[i4] = (qq < NQ) ? src[(size_t)(bi*NQ + qq)*(CCH/4) + (i4 & 127)]
                                : make_float4(0.f,0.f,0.f,0.f);
        }
    }
    __syncthreads();
    int x = t%36, trow = t/36;
    float acc0 = 0.f, acc1 = 0.f;
    for (int c0 = 0; c0 < CCH; c0 += 64) {
        for (int idx = t; idx < 64*36; idx += 288) {
            int r = idx/36, xx = idx%36;
            tile[r*37 + xx] = P[(c0 + r)*HW + xx];
        }
        __syncthreads();
        #pragma unroll 8
        for (int c = 0; c < 64; c++) {
            float pv = tile[c*37 + x];
            acc0 += v1s[trow*CCH + c0 + c]*pv;
            acc1 += v1s[(trow+8)*CCH + c0 + c]*pv;
        }
        __syncthreads();
    }
    att[trow][x]   = acc0*rn1s[x]*(1.f/36.f);
    att[trow+8][x] = acc1*rn1s[x]*(1.f/36.f);
    __syncthreads();
    if (t < 16) {
        float m = -1e30f;
        #pragma unroll
        for (int xx = 0; xx < HW; xx++) m = fmaxf(m, att[t][xx]);
        mx[t] = m;
    }
    __syncthreads();
    att[trow][x]   = expf((att[trow][x]   - mx[trow])*40.f);
    att[trow+8][x] = expf((att[trow+8][x] - mx[trow+8])*40.f);
    __syncthreads();
    if (t < 16) {
        float s = 0.f;
        #pragma unroll
        for (int xx = 0; xx < HW; xx++) s += att[t][xx];
        sm[t] = s;
    }
    __syncthreads();
    att[trow][x]   = att[trow][x]/sm[trow]     + 1.f;
    att[trow+8][x] = att[trow+8][x]/sm[trow+8] + 1.f;
    __syncthreads();
    // pool phase (c-chunk 32, uses first 32 rows of tile)
    int q_a = t >> 5, c_l = t & 31;
    int q_b = q_a + 9;
    float ssq_a = 0.f, ssq_b = 0.f;
    for (int c0 = 0; c0 < CCH; c0 += 32) {
        #pragma unroll
        for (int j = 0; j < 4; j++)
            tile[(trow + 8*j)*37 + x] = P[(c0 + trow + 8*j)*HW + x];
        __syncthreads();
        {
            float a = 0.f;
            #pragma unroll
            for (int xx = 0; xx < HW; xx++) a += tile[c_l*37 + xx]*att[q_a][xx];
            a *= (1.f/36.f);
            v1s[q_a*CCH + c0 + c_l] = a;
            ssq_a += a*a;
        }
        if (q_b < 16) {
            float a = 0.f;
            #pragma unroll
            for (int xx = 0; xx < HW; xx++) a += tile[c_l*37 + xx]*att[q_b][xx];
            a *= (1.f/36.f);
            v1s[q_b*CCH + c0 + c_l] = a;
            ssq_b += a*a;
        }
        __syncthreads();
    }
    #pragma unroll
    for (int off = 16; off > 0; off >>= 1) {
        ssq_a += __shfl_xor_sync(0xffffffffu, ssq_a, off);
        ssq_b += __shfl_xor_sync(0xffffffffu, ssq_b, off);
    }
    int lane = t & 31, warp = t >> 5;
    if (lane == 0) {
        pnfs[warp] = 1.f/fmaxf(sqrtf(ssq_a), 1e-12f);
        if (warp < 7) pnfs[warp + 9] = 1.f/fmaxf(sqrtf(ssq_b), 1e-12f);
    }
    __syncthreads();
    for (int idx = t; idx < 16*CCH; idx += 288) {
        int ql = idx >> 9; int qq = qc + ql;
        if (qq < NQ) g_v1[(size_t)(bi*NQ + qq)*CCH + (idx & 511)] = v1s[idx]*pnfs[ql];
    }
}

// logits GEMM + fused cls_scores
__global__ void __launch_bounds__(128) k_logit(const float* __restrict__ Q,
                                               const float* __restrict__ cw,
                                               const float* __restrict__ cb,
                                               float* __restrict__ out1,
                                               float* __restrict__ out2) {
    int n0 = blockIdx.x*64;
    int t = threadIdx.x;
    int tn = t & 15, tm = t >> 4;
    __shared__ float shAB[2240];
    __shared__ float pools[3*WAY*CCH];
    int bq0 = n0/36;
    {
        float4* dst = (float4*)pools;
        const float4* src = (const float4*)g_v1;
        for (int i4 = t; i4 < 3*WAY*(CCH/4); i4 += 128) {
            int r = i4/640; int rem = i4 - r*640; int i = rem >> 7; int c4 = rem & 127;
            int bq = bq0 + r;
            float4 v = make_float4(0.f,0.f,0.f,0.f);
            if (bq < BB*NQ) {
                int b = bq/NQ, q = bq%NQ;
                v = src[(size_t)((b*WAY + i)*NQ + q)*(CCH/4) + c4];
            }
            dst[i4] = v;
        }
    }
    int nn_l = t & 63, kgrp = t >> 6;
    int nglob = n0 + nn_l;
    bool nval = nglob < NTOT;
    int bq_l = nval ? nglob/36 : 0;
    int x_l  = nval ? nglob%36 : 0;
    const float* qbase = Q + (size_t)bq_l*CHW + x_l;
    int o_a = t >> 1, ka = (t & 1)*8;
    float acc[8][4];
    float accc[4][WAY];
    #pragma unroll
    for (int r = 0; r < 8; r++)
        #pragma unroll
        for (int j = 0; j < 4; j++) acc[r][j] = 0.f;
    #pragma unroll
    for (int j = 0; j < 4; j++)
        #pragma unroll
        for (int i = 0; i < WAY; i++) accc[j][i] = 0.f;
    int rj[4];
    #pragma unroll
    for (int j = 0; j < 4; j++) {
        int n = n0 + tn*4 + j;
        rj[j] = (n < NTOT) ? (n/36 - bq0) : 0;
    }
    for (int k0 = 0; k0 < CCH; k0 += 16) {
        float4 av0 = *(const float4*)(cw + o_a*CCH + k0 + ka);
        float4 av1 = *(const float4*)(cw + o_a*CCH + k0 + ka + 4);
        shAB[(ka+0)*72 + o_a] = av0.x; shAB[(ka+1)*72 + o_a] = av0.y;
        shAB[(ka+2)*72 + o_a] = av0.z; shAB[(ka+3)*72 + o_a] = av0.w;
        shAB[(ka+4)*72 + o_a] = av1.x; shAB[(ka+5)*72 + o_a] = av1.y;
        shAB[(ka+6)*72 + o_a] = av1.z; shAB[(ka+7)*72 + o_a] = av1.w;
        #pragma unroll
        for (int j = 0; j < 8; j++) {
            int kk = kgrp*8 + j;
            shAB[1152 + kk*68 + nn_l] = nval ? qbase[(size_t)(k0 + kk)*HW] : 0.f;
        }
        __syncthreads();
        #pragma unroll
        for (int k = 0; k < 16; k++) {
            float4 af0 = *(const float4*)&shAB[k*72 + tm*8];
            float4 af1 = *(const float4*)&shAB[k*72 + tm*8 + 4];
            float4 bf  = *(const float4*)&shAB[1152 + k*68 + tn*4];
            float am[8] = {af0.x,af0.y,af0.z,af0.w,af1.x,af1.y,af1.z,af1.w};
            float bn[4] = {bf.x,bf.y,bf.z,bf.w};
            #pragma unroll
            for (int r = 0; r < 8; r++)
                #pragma unroll
                for (int j = 0; j < 4; j++) acc[r][j] += am[r]*bn[j];
        }
        #pragma unroll
        for (int kk2 = 0; kk2 < 2; kk2++) {
            int kk = tm*2 + kk2;
            #pragma unroll
            for (int j = 0; j < 4; j++) {
                float bn = shAB[1152 + kk*68 + tn*4 + j];
                #pragma unroll
                for (int i = 0; i < WAY; i++)
                    accc[j][i] += pools[rj[j]*WAY*CCH + i*CCH + k0 + kk]*bn;
            }
        }
        __syncthreads();
    }
    #pragma unroll
    for (int j = 0; j < 4; j++) {
        int n = n0 + tn*4 + j;
        if (n >= NTOT) continue;
        int bq = n/36, x = n%36;
        float av = g_asel[n];
        #pragma unroll
        for (int r = 0; r < 8; r++) {
            int o = tm*8 + r;
            out1[((size_t)bq*NCLS + o)*HW + x] = acc[r][j]*av + cb[o];
        }
    }
    #pragma unroll
    for (int j = 0; j < 4; j++)
        #pragma unroll
        for (int i = 0; i < WAY; i++)
            accc[j][i] += __shfl_xor_sync(0xffffffffu, accc[j][i], 16);
    if ((tm & 1) == 0) {
        int g = tm >> 1;
        #pragma unroll
        for (int j = 0; j < 4; j++)
            #pragma unroll
            for (int i = 0; i < WAY; i++)
                shAB[g*320 + (tn*4 + j)*WAY + i] = accc[j][i];
    }
    __syncthreads();
    for (int idx = t; idx < 320; idx += 128) {
        int n_l = idx/WAY, i = idx%WAY;
        int n = n0 + n_l;
        if (n < NTOT) {
            float s = shAB[idx] + shAB[320 + idx] + shAB[640 + idx] + shAB[960 + idx];
            int bq = n/36, x = n%36;
            out2[((size_t)bq*WAY + i)*HW + x] = 7.f * g_rn2[n] * s;
        }
    }
}

// ---------------- launch ----------------
extern "C" void kernel_launch(void* const* d_in, const int* in_sizes, int n_in,
                              void* d_out, int out_size) {
    (void)in_sizes; (void)n_in; (void)out_size;
    const float* support = (const float*)d_in[0];
    const float* query   = (const float*)d_in[1];
    const float* st      = (const float*)d_in[2];
    const float* qt      = (const float*)d_in[3];
    const float* w1      = (const float*)d_in[4];
    const float* b1      = (const float*)d_in[5];
    const float* gam     = (const float*)d_in[6];
    const float* bet     = (const float*)d_in[7];
    const float* w2      = (const float*)d_in[8];
    const float* b2      = (const float*)d_in[9];
    const float* cw      = (const float*)d_in[10];
    const float* cb      = (const float*)d_in[11];
    float* out1 = (float*)d_out;                               // logits 600*64*36
    float* out2 = out1 + (size_t)BB*NQ*NCLS*HW;                // cls_scores 600*5*36

    k_protos   <<<dim3(16, BB), 288>>>(support, st);
    k_prep1    <<<BB*WAY, 288>>>();
    k_prep2ch1 <<<BB*NQ, 288>>>(query, w1, b1);
    k_ch2f     <<<dim3(BB*WAY, 5), 576>>>(w1, b1);
    k_awv2     <<<dim3(BB*WAY, 3), 288>>>(gam, bet, w2, b2);
    k_v1s2     <<<BB*NQ, 288>>>(query, qt);
    k_s1pool   <<<dim3(BB*WAY, 5), 288>>>();
    k_logit    <<<(NTOT + 63)/64, 128>>>(query, cw, cb, out1, out2);
}

// round 16
// speedup vs baseline: 1.0477x; 1.0477x over previous
#include <cuda_runtime.h>
#include <math.h>

#define BB   8
#define NS   25
#define NQ   75
#define WAY  5
#define CCH  512
#define HW   36
#define MID  6
#define NCLS 64
#define PAIRS (BB*WAY*NQ)   /* 3000 */
#define CHW  (CCH*HW)       /* 18432 */
#define CHW4 (CHW/4)        /* 4608 */
#define NTOT (BB*NQ*HW)     /* 21600 */

// ---------------- scratch ----------------
__device__ float g_protos[BB*WAY*CHW];     // [b,i,c,x]
__device__ float g_rn1 [BB*WAY*HW];
__device__ float g_mw1 [BB*WAY*CCH];
__device__ float g_rn2 [BB*NQ*HW];
__device__ float g_mw2 [BB*NQ*CCH];
__device__ float g_yv  [2*PAIRS*MID];
__device__ float g_stats[24];
__device__ float g_wv1 [PAIRS*HW];
__device__ float g_v1  [PAIRS*CCH];        // v1, later NORMALIZED pooled
__device__ float g_v2  [PAIRS*CCH];
__device__ float g_asel[BB*NQ*HW];

// prototypes (float4) + zero stats
__global__ void __launch_bounds__(288) k_protos(const float* __restrict__ sup,
                                                const float* __restrict__ st) {
    int b = blockIdx.y, t = threadIdx.x;
    if (blockIdx.x == 0 && b == 0 && t < 24) g_stats[t] = 0.f;
    __shared__ float sts[NS*WAY];
    __shared__ float rcnt[WAY];
    if (t < NS*WAY) sts[t] = st[b*NS*WAY + t];
    __syncthreads();
    if (t < WAY) { float s = 0.f; for (int n = 0; n < NS; n++) s += sts[n*WAY + t]; rcnt[t] = 1.f/s; }
    __syncthreads();
    int d4 = blockIdx.x*288 + t;
    const float4* sb = (const float4*)sup + (size_t)b*NS*CHW4 + d4;
    float4 acc[WAY];
    #pragma unroll
    for (int w = 0; w < WAY; w++) acc[w] = make_float4(0.f,0.f,0.f,0.f);
    for (int n = 0; n < NS; n++) {
        float4 v = sb[(size_t)n*CHW4];
        #pragma unroll
        for (int w = 0; w < WAY; w++) {
            float s = sts[n*WAY + w];
            acc[w].x += s*v.x; acc[w].y += s*v.y; acc[w].z += s*v.z; acc[w].w += s*v.w;
        }
    }
    #pragma unroll
    for (int w = 0; w < WAY; w++) {
        float r = rcnt[w];
        float4 o = make_float4(acc[w].x*r, acc[w].y*r, acc[w].z*r, acc[w].w*r);
        ((float4*)g_protos)[(size_t)(b*WAY + w)*CHW4 + d4] = o;
    }
}

// per (b,i): rn1, mw1
__global__ void __launch_bounds__(288) k_prep1() {
    int bi = blockIdx.x, t = threadIdx.x;
    const float4* P4 = (const float4*)(g_protos + (size_t)bi*CHW);
    __shared__ float part[288*4];
    __shared__ float rn1s[HW];
    float s0=0.f,s1=0.f,s2=0.f,s3=0.f;
    #pragma unroll 4
    for (int k = 0; k < 16; k++) {
        float4 v = P4[t + 288*k];
        s0 += v.x*v.x; s1 += v.y*v.y; s2 += v.z*v.z; s3 += v.w*v.w;
    }
    part[4*t]=s0; part[4*t+1]=s1; part[4*t+2]=s2; part[4*t+3]=s3;
    __syncthreads();
    if (t < HW) {
        int y4 = t >> 2, j = t & 3;
        float s = 0.f;
        #pragma unroll
        for (int m = 0; m < 32; m++) s += part[4*(y4 + 9*m) + j];
        float r = 1.f/fmaxf(sqrtf(s), 1e-12f);
        rn1s[t] = r; g_rn1[bi*HW + t] = r;
    }
    __syncthreads();
    for (int c = t; c < CCH; c += 288) {
        const float4* row = P4 + c*9;
        float a = 0.f;
        #pragma unroll
        for (int y4 = 0; y4 < 9; y4++) {
            float4 v = row[y4];
            a += v.x*rn1s[y4*4] + v.y*rn1s[y4*4+1] + v.z*rn1s[y4*4+2] + v.w*rn1s[y4*4+3];
        }
        g_mw1[bi*CCH + c] = a*(1.f/36.f);
    }
}

// fused prep2 + ch1(path1 conv1); per bq; writes rn2, mw2
__global__ void __launch_bounds__(288) k_prep2ch1(const float* __restrict__ Q,
                                                  const float* __restrict__ w1,
                                                  const float* __restrict__ b1) {
    int bq = blockIdx.x; int b = bq/NQ, q = bq%NQ;
    int t = threadIdx.x;
    __shared__ float mw1s[WAY*CCH];
    __shared__ float redA[20][288];
    __shared__ float part[288*4];
    __shared__ float rn2s[HW];
    __shared__ float ch1s[WAY][HW];
    {
        const float4* src = (const float4*)(g_mw1 + b*WAY*CCH);
        float4* dst = (float4*)mw1s;
        for (int i4 = t; i4 < WAY*CCH/4; i4 += 288) dst[i4] = src[i4];
    }
    __syncthreads();
    const float4* Q4 = (const float4*)(Q + (size_t)bq*CHW);
    float aacc[WAY][4];
    float sq[4] = {0.f,0.f,0.f,0.f};
    #pragma unroll
    for (int i = 0; i < WAY; i++)
        #pragma unroll
        for (int j = 0; j < 4; j++) aacc[i][j] = 0.f;
    #pragma unroll 4
    for (int k = 0; k < 16; k++) {
        int idx = t + 288*k;
        int c = idx/9;
        float4 v = Q4[idx];
        sq[0] += v.x*v.x; sq[1] += v.y*v.y; sq[2] += v.z*v.z; sq[3] += v.w*v.w;
        #pragma unroll
        for (int i = 0; i < WAY; i++) {
            float w = mw1s[i*CCH + c];
            aacc[i][0] += w*v.x; aacc[i][1] += w*v.y; aacc[i][2] += w*v.z; aacc[i][3] += w*v.w;
        }
    }
    #pragma unroll
    for (int j = 0; j < 4; j++) part[4*t + j] = sq[j];
    #pragma unroll
    for (int i = 0; i < WAY; i++)
        #pragma unroll
        for (int j = 0; j < 4; j++) redA[i*4 + j][t] = aacc[i][j];
    __syncthreads();
    if (t < HW) {
        int y4 = t >> 2, j = t & 3;
        float s = 0.f;
        #pragma unroll
        for (int m = 0; m < 32; m++) s += part[4*(y4 + 9*m) + j];
        float r = 1.f/fmaxf(sqrtf(s), 1e-12f);
        rn2s[t] = r; g_rn2[bq*HW + t] = r;
    }
    __syncthreads();
    if (t < WAY*HW) {
        int i = t/HW, y = t%HW;
        int y4 = y >> 2, j = y & 3;
        float s = 0.f;
        #pragma unroll
        for (int m = 0; m < 32; m++) s += redA[i*4 + j][y4 + 9*m];
        ch1s[i][y] = s*rn2s[y];
    }
    // pass2: mw2 (Q rows L1-resident)
    for (int c = t; c < CCH; c += 288) {
        const float4* row = Q4 + c*9;
        float a = 0.f;
        #pragma unroll
        for (int y4 = 0; y4 < 9; y4++) {
            float4 v = row[y4];
            a += v.x*rn2s[y4*4] + v.y*rn2s[y4*4+1] + v.z*rn2s[y4*4+2] + v.w*rn2s[y4*4+3];
        }
        g_mw2[bq*CCH + c] = a*(1.f/36.f);
    }
    __syncthreads();
    if (t < WAY*MID) {  // path1 conv1
        int i = t/MID, m = t%MID;
        float a = b1[m];
        #pragma unroll
        for (int y = 0; y < HW; y++) a += w1[m*HW + y]*ch1s[i][y];
        int p = (b*WAY + i)*NQ + q;
        g_yv[p*MID + m] = a;
        atomicAdd(&g_stats[m], a); atomicAdd(&g_stats[MID + m], a*a);
    }
}

// path2 conv input + conv1 + BN stats; per (bi, q-chunk16); smem-tiled P (c-chunk 64)
// 288 threads, 2 outputs/thread (tile reuse), mw2 read via LDS.128 (4 c per load)
__global__ void __launch_bounds__(288) k_ch2f(const float* __restrict__ w1,
                                              const float* __restrict__ b1) {
    int bi = blockIdx.x; int qc = blockIdx.y*16;
    int b = bi/WAY;
    const float* P = g_protos + (size_t)bi*CHW;
    __shared__ float mw2s[16*CCH];   // 32KB
    __shared__ float tile[64*37];    // 9.47KB
    __shared__ float ch2s[16][HW];
    __shared__ float rn1s[HW];
    int t = threadIdx.x;
    if (t < HW) rn1s[t] = g_rn1[bi*HW + t];
    {
        float4* dst = (float4*)mw2s;
        const float4* src = (const float4*)g_mw2;
        for (int i4 = t; i4 < 16*128; i4 += 288) {
            int ql = i4 >> 7; int qq = qc + ql;
            dst[i4] = (qq < NQ) ? src[(size_t)(b*NQ + qq)*128 + (i4 & 127)]
                                : make_float4(0.f,0.f,0.f,0.f);
        }
    }
    __syncthreads();
    int q0 = t/36, x0 = t%36;          // thread owns (q0,x0) and (q0+8,x0)
    int q1 = q0 + 8;
    float acc0 = 0.f, acc1 = 0.f;
    for (int c0 = 0; c0 < CCH; c0 += 64) {
        for (int idx = t; idx < 64*36; idx += 288) {
            int r = idx/36, xx = idx%36;
            tile[r*37 + xx] = P[(c0 + r)*HW + xx];
        }
        __syncthreads();
        const float4* m0p = (const float4*)(mw2s + q0*CCH + c0);
        const float4* m1p = (const float4*)(mw2s + q1*CCH + c0);
        #pragma unroll 4
        for (int c4 = 0; c4 < 16; c4++) {
            float4 m0 = m0p[c4];
            float4 m1 = m1p[c4];
            float p0 = tile[(c4*4+0)*37 + x0];
            float p1 = tile[(c4*4+1)*37 + x0];
            float p2 = tile[(c4*4+2)*37 + x0];
            float p3 = tile[(c4*4+3)*37 + x0];
            acc0 += m0.x*p0; acc0 += m0.y*p1; acc0 += m0.z*p2; acc0 += m0.w*p3;
            acc1 += m1.x*p0; acc1 += m1.y*p1; acc1 += m1.z*p2; acc1 += m1.w*p3;
        }
        __syncthreads();
    }
    ch2s[q0][x0] = acc0*rn1s[x0];
    ch2s[q1][x0] = acc1*rn1s[x0];
    __syncthreads();
    if (t < 16*MID) {
        int g2 = t/MID, m = t%MID; int q2 = qc + g2;
        if (q2 < NQ) {
            float s = b1[m];
            #pragma unroll
            for (int xx = 0; xx < HW; xx++) s += w1[m*HW + xx]*ch2s[g2][xx];
            int p = bi*NQ + q2;
            g_yv[PAIRS*MID + p*MID + m] = s;
            atomicAdd(&g_stats[12 + m], s); atomicAdd(&g_stats[18 + m], s*s);
        }
    }
}

// fused BN-finalize + conv2 (aw) + v2 matvec; per (bi, q-chunk25); c-chunk 64
__global__ void __launch_bounds__(288) k_awv2(const float* __restrict__ gam,
                                              const float* __restrict__ bet,
                                              const float* __restrict__ w2,
                                              const float* __restrict__ b2) {
    int bi = blockIdx.x; int qc = blockIdx.y*25;
    int b = bi/WAY;
    int pb = bi*NQ + qc;
    const float* P = g_protos + (size_t)bi*CHW;
    __shared__ float bnps[24];
    __shared__ float hsh[25][12];
    __shared__ float wv2s[25*HW];
    __shared__ float tile[64*37];
    __shared__ float rn1s[HW];
    int t = threadIdx.x;
    if (t < 12) {
        int path = t/MID, m = t%MID;
        float sum = g_stats[path*12 + m];
        float sqs = g_stats[path*12 + MID + m];
        float mu  = sum/(float)PAIRS;
        float var = sqs/(float)PAIRS - mu*mu;
        bnps[path*12 + m]       = mu;
        bnps[path*12 + MID + m] = rsqrtf(var + 1e-5f);
    }
    if (t >= 64 && t < 64 + HW) rn1s[t - 64] = g_rn1[bi*HW + (t - 64)];
    __syncthreads();
    for (int idx = t; idx < 300; idx += 288) {   // cover all 25 pairs
        int pl = idx/12, tt = idx%12, path = tt/MID, m = tt%MID;
        int p = pb + pl;
        float v = g_yv[path*PAIRS*MID + p*MID + m];
        float z = gam[m]*(v - bnps[path*12 + m])*bnps[path*12 + MID + m] + bet[m];
        hsh[pl][tt] = fmaxf(z, 0.f);
    }
    __syncthreads();
    for (int idx = t; idx < 25*72; idx += 288) {
        int pl = idx/72, tt = idx%72, path = tt/HW, k = tt%HW;
        int p = pb + pl; int bq = b*NQ + qc + pl;
        float a = b2[k];
        #pragma unroll
        for (int m = 0; m < MID; m++) a += w2[k*MID + m]*hsh[pl][path*MID + m];
        if (path == 0) g_wv1[p*HW + k] = a * g_rn2[bq*HW + k];
        else           wv2s[pl*HW + k] = a * rn1s[k];
    }
    __syncthreads();
    // v2[p,c] = sum_x P[c,x]*wv2[p,x]
    for (int c0 = 0; c0 < CCH; c0 += 64) {
        for (int idx = t; idx < 64*36; idx += 288) {
            int r = idx/36, xx = idx%36;
            tile[r*37 + xx] = P[(c0 + r)*HW + xx];
        }
        __syncthreads();
        #pragma unroll
        for (int r = 0; r < 6; r++) {
            int item = t + 288*r;
            if (item < 1600) {
                int q = item >> 6, c_l = item & 63;
                float a = 0.f;
                #pragma unroll
                for (int xx = 0; xx < HW; xx++) a += tile[c_l*37 + xx]*wv2s[q*HW + xx];
                g_v2[(size_t)(pb + q)*CCH + c0 + c_l] = a;
            }
        }
        __syncthreads();
    }
}

// fused v1 + s2 + attsel; per bq, smem-tiled Q pass (c-chunk 64)
__global__ void __launch_bounds__(288) k_v1s2(const float* __restrict__ Q,
                                              const float* __restrict__ qt) {
    int bq = blockIdx.x; int b = bq/NQ, q = bq%NQ;
    int t = threadIdx.x;
    __shared__ float v2s[WAY*CCH];
    __shared__ float wv1s[WAY][HW];
    __shared__ float tile[64*37];
    __shared__ float rn2s[HW];
    __shared__ float s2s[WAY][HW];
    __shared__ float mx[WAY], sm[WAY], qts[WAY];
    {
        float4* dst = (float4*)v2s;
        for (int i4 = t; i4 < WAY*CCH/4; i4 += 288) {
            int i = i4/(CCH/4);
            const float4* src = (const float4*)(g_v2 + (size_t)((b*WAY + i)*NQ + q)*CCH);
            dst[i4] = src[i4 - i*(CCH/4)];
        }
    }
    if (t < WAY*HW) wv1s[t/HW][t%HW] = g_wv1[((b*WAY + t/HW)*NQ + q)*HW + t%HW];
    if (t < HW) rn2s[t] = g_rn2[bq*HW + t];
    if (t < WAY) qts[t] = qt[(size_t)bq*WAY + t];
    __syncthreads();
    const float* Qb = Q + (size_t)bq*CHW;
    int si = (t < 180) ? t/36 : 0;
    int sx = t%36;
    float s2a = 0.f;
    for (int c0 = 0; c0 < CCH; c0 += 64) {
        for (int idx = t; idx < 64*36; idx += 288) {
            int r = idx/36, xx = idx%36;
            tile[r*37 + xx] = Qb[(c0 + r)*HW + xx];
        }
        __syncthreads();
        #pragma unroll
        for (int r = 0; r < 2; r++) {
            int item = t + 288*r;
            if (item < 320) {
                int i = item >> 6, c_l = item & 63;
                float a = 0.f;
                #pragma unroll
                for (int y = 0; y < HW; y++) a += tile[c_l*37 + y]*wv1s[i][y];
                g_v1[(size_t)((b*WAY + i)*NQ + q)*CCH + c0 + c_l] = a;
            }
        }
        if (t < 180) {
            #pragma unroll 8
            for (int c = 0; c < 64; c++) s2a += v2s[si*CCH + c0 + c]*tile[c*37 + sx];
        }
        __syncthreads();
    }
    if (t < 180) s2s[si][sx] = s2a * rn2s[sx] * (1.f/36.f);
    __syncthreads();
    if (t < WAY) {
        float m = -1e30f;
        #pragma unroll
        for (int yy = 0; yy < HW; yy++) m = fmaxf(m, s2s[t][yy]);
        mx[t] = m;
    }
    __syncthreads();
    if (t < 180) s2s[si][sx] = expf((s2s[si][sx] - mx[si])*40.f);
    __syncthreads();
    if (t < WAY) {
        float s = 0.f;
        #pragma unroll
        for (int yy = 0; yy < HW; yy++) s += s2s[t][yy];
        sm[t] = s;
    }
    __syncthreads();
    if (t < HW) {
        float a = 0.f;
        #pragma unroll
        for (int i = 0; i < WAY; i++) a += (s2s[i][t]/sm[i] + 1.f)*qts[i];
        g_asel[bq*HW + t] = a;
    }
}

// fused s1 + softmax + proto-pool + l2norm; per (bi, q-chunk16)
__global__ void __launch_bounds__(288) k_s1pool() {
    int bi = blockIdx.x; int qc = blockIdx.y*16;
    const float* P = g_protos + (size_t)bi*CHW;
    __shared__ float v1s[16*CCH];
    __shared__ float tile[64*37];
    __shared__ float att[16][HW];
    __shared__ float rn1s[HW];
    __shared__ float mx[16], sm[16];
    __shared__ float pnfs[16];
    int t = threadIdx.x;
    if (t < HW) rn1s[t] = g_rn1[bi*HW + t];
    {
        float4* dst = (float4*)v1s;
        const float4* src = (const float4*)g_v1;
        for (int i4 = t; i4 < 16*CCH/4; i4 += 288) {
            int ql = i4 >> 7;
            int qq = qc + ql;
            dst[i4] = (qq < NQ) ? src[(size_t)(bi*NQ + qq)*(CCH/4) + (i4 & 127)]
                                : make_float4(0.f,0.f,0.f,0.f);
        }
    }
    __syncthreads();
    int x = t%36, trow = t/36;
    float acc0 = 0.f, acc1 = 0.f;
    for (int c0 = 0; c0 < CCH; c0 += 64) {
        for (int idx = t; idx < 64*36; idx += 288) {
            int r = idx/36, xx = idx%36;
            tile[r*37 + xx] = P[(c0 + r)*HW + xx];
        }
        __syncthreads();
        #pragma unroll 8
        for (int c = 0; c < 64; c++) {
            float pv = tile[c*37 + x];
            acc0 += v1s[trow*CCH + c0 + c]*pv;
            acc1 += v1s[(trow+8)*CCH + c0 + c]*pv;
        }
        __syncthreads();
    }
    att[trow][x]   = acc0*rn1s[x]*(1.f/36.f);
    att[trow+8][x] = acc1*rn1s[x]*(1.f/36.f);
    __syncthreads();
    if (t < 16) {
        float m = -1e30f;
        #pragma unroll
        for (int xx = 0; xx < HW; xx++) m = fmaxf(m, att[t][xx]);
        mx[t] = m;
    }
    __syncthreads();
    att[trow][x]   = expf((att[trow][x]   - mx[trow])*40.f);
    att[trow+8][x] = expf((att[trow+8][x] - mx[trow+8])*40.f);
    __syncthreads();
    if (t < 16) {
        float s = 0.f;
        #pragma unroll
        for (int xx = 0; xx < HW; xx++) s += att[t][xx];
        sm[t] = s;
    }
    __syncthreads();
    att[trow][x]   = att[trow][x]/sm[trow]     + 1.f;
    att[trow+8][x] = att[trow+8][x]/sm[trow+8] + 1.f;
    __syncthreads();
    // pool phase (c-chunk 32, uses first 32 rows of tile)
    int q_a = t >> 5, c_l = t & 31;
    int q_b = q_a + 9;
    float ssq_a = 0.f, ssq_b = 0.f;
    for (int c0 = 0; c0 < CCH; c0 += 32) {
        #pragma unroll
        for (int j = 0; j < 4; j++)
            tile[(trow + 8*j)*37 + x] = P[(c0 + trow + 8*j)*HW + x];
        __syncthreads();
        {
            float a = 0.f;
            #pragma unroll
            for (int xx = 0; xx < HW; xx++) a += tile[c_l*37 + xx]*att[q_a][xx];
            a *= (1.f/36.f);
            v1s[q_a*CCH + c0 + c_l] = a;
            ssq_a += a*a;
        }
        if (q_b < 16) {
            float a = 0.f;
            #pragma unroll
            for (int xx = 0; xx < HW; xx++) a += tile[c_l*37 + xx]*att[q_b][xx];
            a *= (1.f/36.f);
            v1s[q_b*CCH + c0 + c_l] = a;
            ssq_b += a*a;
        }
        __syncthreads();
    }
    #pragma unroll
    for (int off = 16; off > 0; off >>= 1) {
        ssq_a += __shfl_xor_sync(0xffffffffu, ssq_a, off);
        ssq_b += __shfl_xor_sync(0xffffffffu, ssq_b, off);
    }
    int lane = t & 31, warp = t >> 5;
    if (lane == 0) {
        pnfs[warp] = 1.f/fmaxf(sqrtf(ssq_a), 1e-12f);
        if (warp < 7) pnfs[warp + 9] = 1.f/fmaxf(sqrtf(ssq_b), 1e-12f);
    }
    __syncthreads();
    for (int idx = t; idx < 16*CCH; idx += 288) {
        int ql = idx >> 9; int qq = qc + ql;
        if (qq < NQ) g_v1[(size_t)(bi*NQ + qq)*CCH + (idx & 511)] = v1s[idx]*pnfs[ql];
    }
}

// logits GEMM + fused cls_scores
__global__ void __launch_bounds__(128) k_logit(const float* __restrict__ Q,
                                               const float* __restrict__ cw,
                                               const float* __restrict__ cb,
                                               float* __restrict__ out1,
                                               float* __restrict__ out2) {
    int n0 = blockIdx.x*64;
    int t = threadIdx.x;
    int tn = t & 15, tm = t >> 4;
    __shared__ float shAB[2240];
    __shared__ float pools[3*WAY*CCH];
    int bq0 = n0/36;
    {
        float4* dst = (float4*)pools;
        const float4* src = (const float4*)g_v1;
        for (int i4 = t; i4 < 3*WAY*(CCH/4); i4 += 128) {
            int r = i4/640; int rem = i4 - r*640; int i = rem >> 7; int c4 = rem & 127;
            int bq = bq0 + r;
            float4 v = make_float4(0.f,0.f,0.f,0.f);
            if (bq < BB*NQ) {
                int b = bq/NQ, q = bq%NQ;
                v = src[(size_t)((b*WAY + i)*NQ + q)*(CCH/4) + c4];
            }
            dst[i4] = v;
        }
    }
    int nn_l = t & 63, kgrp = t >> 6;
    int nglob = n0 + nn_l;
    bool nval = nglob < NTOT;
    int bq_l = nval ? nglob/36 : 0;
    int x_l  = nval ? nglob%36 : 0;
    const float* qbase = Q + (size_t)bq_l*CHW + x_l;
    int o_a = t >> 1, ka = (t & 1)*8;
    float acc[8][4];
    float accc[4][WAY];
    #pragma unroll
    for (int r = 0; r < 8; r++)
        #pragma unroll
        for (int j = 0; j < 4; j++) acc[r][j] = 0.f;
    #pragma unroll
    for (int j = 0; j < 4; j++)
        #pragma unroll
        for (int i = 0; i < WAY; i++) accc[j][i] = 0.f;
    int rj[4];
    #pragma unroll
    for (int j = 0; j < 4; j++) {
        int n = n0 + tn*4 + j;
        rj[j] = (n < NTOT) ? (n/36 - bq0) : 0;
    }
    for (int k0 = 0; k0 < CCH; k0 += 16) {
        float4 av0 = *(const float4*)(cw + o_a*CCH + k0 + ka);
        float4 av1 = *(const float4*)(cw + o_a*CCH + k0 + ka + 4);
        shAB[(ka+0)*72 + o_a] = av0.x; shAB[(ka+1)*72 + o_a] = av0.y;
        shAB[(ka+2)*72 + o_a] = av0.z; shAB[(ka+3)*72 + o_a] = av0.w;
        shAB[(ka+4)*72 + o_a] = av1.x; shAB[(ka+5)*72 + o_a] = av1.y;
        shAB[(ka+6)*72 + o_a] = av1.z; shAB[(ka+7)*72 + o_a] = av1.w;
        #pragma unroll
        for (int j = 0; j < 8; j++) {
            int kk = kgrp*8 + j;
            shAB[1152 + kk*68 + nn_l] = nval ? qbase[(size_t)(k0 + kk)*HW] : 0.f;
        }
        __syncthreads();
        #pragma unroll
        for (int k = 0; k < 16; k++) {
            float4 af0 = *(const float4*)&shAB[k*72 + tm*8];
            float4 af1 = *(const float4*)&shAB[k*72 + tm*8 + 4];
            float4 bf  = *(const float4*)&shAB[1152 + k*68 + tn*4];
            float am[8] = {af0.x,af0.y,af0.z,af0.w,af1.x,af1.y,af1.z,af1.w};
            float bn[4] = {bf.x,bf.y,bf.z,bf.w};
            #pragma unroll
            for (int r = 0; r < 8; r++)
                #pragma unroll
                for (int j = 0; j < 4; j++) acc[r][j] += am[r]*bn[j];
        }
        #pragma unroll
        for (int kk2 = 0; kk2 < 2; kk2++) {
            int kk = tm*2 + kk2;
            #pragma unroll
            for (int j = 0; j < 4; j++) {
                float bn = shAB[1152 + kk*68 + tn*4 + j];
                #pragma unroll
                for (int i = 0; i < WAY; i++)
                    accc[j][i] += pools[rj[j]*WAY*CCH + i*CCH + k0 + kk]*bn;
            }
        }
        __syncthreads();
    }
    #pragma unroll
    for (int j = 0; j < 4; j++) {
        int n = n0 + tn*4 + j;
        if (n >= NTOT) continue;
        int bq = n/36, x = n%36;
        float av = g_asel[n];
        #pragma unroll
        for (int r = 0; r < 8; r++) {
            int o = tm*8 + r;
            out1[((size_t)bq*NCLS + o)*HW + x] = acc[r][j]*av + cb[o];
        }
    }
    #pragma unroll
    for (int j = 0; j < 4; j++)
        #pragma unroll
        for (int i = 0; i < WAY; i++)
            accc[j][i] += __shfl_xor_sync(0xffffffffu, accc[j][i], 16);
    if ((tm & 1) == 0) {
        int g = tm >> 1;
        #pragma unroll
        for (int j = 0; j < 4; j++)
            #pragma unroll
            for (int i = 0; i < WAY; i++)
                shAB[g*320 + (tn*4 + j)*WAY + i] = accc[j][i];
    }
    __syncthreads();
    for (int idx = t; idx < 320; idx += 128) {
        int n_l = idx/WAY, i = idx%WAY;
        int n = n0 + n_l;
        if (n < NTOT) {
            float s = shAB[idx] + shAB[320 + idx] + shAB[640 + idx] + shAB[960 + idx];
            int bq = n/36, x = n%36;
            out2[((size_t)bq*WAY + i)*HW + x] = 7.f * g_rn2[n] * s;
        }
    }
}

// ---------------- launch ----------------
extern "C" void kernel_launch(void* const* d_in, const int* in_sizes, int n_in,
                              void* d_out, int out_size) {
    (void)in_sizes; (void)n_in; (void)out_size;
    const float* support = (const float*)d_in[0];
    const float* query   = (const float*)d_in[1];
    const float* st      = (const float*)d_in[2];
    const float* qt      = (const float*)d_in[3];
    const float* w1      = (const float*)d_in[4];
    const float* b1      = (const float*)d_in[5];
    const float* gam     = (const float*)d_in[6];
    const float* bet     = (const float*)d_in[7];
    const float* w2      = (const float*)d_in[8];
    const float* b2      = (const float*)d_in[9];
    const float* cw      = (const float*)d_in[10];
    const float* cb      = (const float*)d_in[11];
    float* out1 = (float*)d_out;                               // logits 600*64*36
    float* out2 = out1 + (size_t)BB*NQ*NCLS*HW;                // cls_scores 600*5*36

    k_protos   <<<dim3(16, BB), 288>>>(support, st);
    k_prep1    <<<BB*WAY, 288>>>();
    k_prep2ch1 <<<BB*NQ, 288>>>(query, w1, b1);
    k_ch2f     <<<dim3(BB*WAY, 5), 288>>>(w1, b1);
    k_awv2     <<<dim3(BB*WAY, 3), 288>>>(gam, bet, w2, b2);
    k_v1s2     <<<BB*NQ, 288>>>(query, qt);
    k_s1pool   <<<dim3(BB*WAY, 5), 288>>>();
    k_logit    <<<(NTOT + 63)/64, 128>>>(query, cw, cb, out1, out2);
}

// round 17
// speedup vs baseline: 1.0752x; 1.0262x over previous
#include <cuda_runtime.h>
#include <math.h>

#define BB   8
#define NS   25
#define NQ   75
#define WAY  5
#define CCH  512
#define HW   36
#define MID  6
#define NCLS 64
#define PAIRS (BB*WAY*NQ)   /* 3000 */
#define CHW  (CCH*HW)       /* 18432 */
#define CHW4 (CHW/4)        /* 4608 */
#define NTOT (BB*NQ*HW)     /* 21600 */

// ---------------- scratch ----------------
__device__ float g_protos[BB*WAY*CHW];     // [b,i,c,x]
__device__ float g_rn1 [BB*WAY*HW];
__device__ float g_mw1 [BB*WAY*CCH];
__device__ float g_rn2 [BB*NQ*HW];
__device__ float g_mw2 [BB*NQ*CCH];
__device__ float g_yv  [2*PAIRS*MID];
__device__ float g_stats[24];
__device__ float g_wv1 [PAIRS*HW];
__device__ float g_v1  [PAIRS*CCH];        // v1, later NORMALIZED pooled
__device__ float g_v2  [PAIRS*CCH];
__device__ float g_asel[BB*NQ*HW];

// prototypes (float4) + zero stats
__global__ void __launch_bounds__(288) k_protos(const float* __restrict__ sup,
                                                const float* __restrict__ st) {
    int b = blockIdx.y, t = threadIdx.x;
    if (blockIdx.x == 0 && b == 0 && t < 24) g_stats[t] = 0.f;
    __shared__ float sts[NS*WAY];
    __shared__ float rcnt[WAY];
    if (t < NS*WAY) sts[t] = st[b*NS*WAY + t];
    __syncthreads();
    if (t < WAY) { float s = 0.f; for (int n = 0; n < NS; n++) s += sts[n*WAY + t]; rcnt[t] = 1.f/s; }
    __syncthreads();
    int d4 = blockIdx.x*288 + t;
    const float4* sb = (const float4*)sup + (size_t)b*NS*CHW4 + d4;
    float4 acc[WAY];
    #pragma unroll
    for (int w = 0; w < WAY; w++) acc[w] = make_float4(0.f,0.f,0.f,0.f);
    for (int n = 0; n < NS; n++) {
        float4 v = sb[(size_t)n*CHW4];
        #pragma unroll
        for (int w = 0; w < WAY; w++) {
            float s = sts[n*WAY + w];
            acc[w].x += s*v.x; acc[w].y += s*v.y; acc[w].z += s*v.z; acc[w].w += s*v.w;
        }
    }
    #pragma unroll
    for (int w = 0; w < WAY; w++) {
        float r = rcnt[w];
        float4 o = make_float4(acc[w].x*r, acc[w].y*r, acc[w].z*r, acc[w].w*r);
        ((float4*)g_protos)[(size_t)(b*WAY + w)*CHW4 + d4] = o;
    }
}

// per (b,i): rn1, mw1
__global__ void __launch_bounds__(288) k_prep1() {
    int bi = blockIdx.x, t = threadIdx.x;
    const float4* P4 = (const float4*)(g_protos + (size_t)bi*CHW);
    __shared__ float part[288*4];
    __shared__ float rn1s[HW];
    float s0=0.f,s1=0.f,s2=0.f,s3=0.f;
    #pragma unroll 4
    for (int k = 0; k < 16; k++) {
        float4 v = P4[t + 288*k];
        s0 += v.x*v.x; s1 += v.y*v.y; s2 += v.z*v.z; s3 += v.w*v.w;
    }
    part[4*t]=s0; part[4*t+1]=s1; part[4*t+2]=s2; part[4*t+3]=s3;
    __syncthreads();
    if (t < HW) {
        int y4 = t >> 2, j = t & 3;
        float s = 0.f;
        #pragma unroll
        for (int m = 0; m < 32; m++) s += part[4*(y4 + 9*m) + j];
        float r = 1.f/fmaxf(sqrtf(s), 1e-12f);
        rn1s[t] = r; g_rn1[bi*HW + t] = r;
    }
    __syncthreads();
    for (int c = t; c < CCH; c += 288) {
        const float4* row = P4 + c*9;
        float a = 0.f;
        #pragma unroll
        for (int y4 = 0; y4 < 9; y4++) {
            float4 v = row[y4];
            a += v.x*rn1s[y4*4] + v.y*rn1s[y4*4+1] + v.z*rn1s[y4*4+2] + v.w*rn1s[y4*4+3];
        }
        g_mw1[bi*CCH + c] = a*(1.f/36.f);
    }
}

// fused prep2 + ch1(path1 conv1); per bq; writes rn2, mw2
__global__ void __launch_bounds__(288) k_prep2ch1(const float* __restrict__ Q,
                                                  const float* __restrict__ w1,
                                                  const float* __restrict__ b1) {
    int bq = blockIdx.x; int b = bq/NQ, q = bq%NQ;
    int t = threadIdx.x;
    __shared__ float mw1s[WAY*CCH];
    __shared__ float redA[20][288];
    __shared__ float part[288*4];
    __shared__ float rn2s[HW];
    __shared__ float ch1s[WAY][HW];
    {
        const float4* src = (const float4*)(g_mw1 + b*WAY*CCH);
        float4* dst = (float4*)mw1s;
        for (int i4 = t; i4 < WAY*CCH/4; i4 += 288) dst[i4] = src[i4];
    }
    __syncthreads();
    const float4* Q4 = (const float4*)(Q + (size_t)bq*CHW);
    float aacc[WAY][4];
    float sq[4] = {0.f,0.f,0.f,0.f};
    #pragma unroll
    for (int i = 0; i < WAY; i++)
        #pragma unroll
        for (int j = 0; j < 4; j++) aacc[i][j] = 0.f;
    #pragma unroll 4
    for (int k = 0; k < 16; k++) {
        int idx = t + 288*k;
        int c = idx/9;
        float4 v = Q4[idx];
        sq[0] += v.x*v.x; sq[1] += v.y*v.y; sq[2] += v.z*v.z; sq[3] += v.w*v.w;
        #pragma unroll
        for (int i = 0; i < WAY; i++) {
            float w = mw1s[i*CCH + c];
            aacc[i][0] += w*v.x; aacc[i][1] += w*v.y; aacc[i][2] += w*v.z; aacc[i][3] += w*v.w;
        }
    }
    #pragma unroll
    for (int j = 0; j < 4; j++) part[4*t + j] = sq[j];
    #pragma unroll
    for (int i = 0; i < WAY; i++)
        #pragma unroll
        for (int j = 0; j < 4; j++) redA[i*4 + j][t] = aacc[i][j];
    __syncthreads();
    if (t < HW) {
        int y4 = t >> 2, j = t & 3;
        float s = 0.f;
        #pragma unroll
        for (int m = 0; m < 32; m++) s += part[4*(y4 + 9*m) + j];
        float r = 1.f/fmaxf(sqrtf(s), 1e-12f);
        rn2s[t] = r; g_rn2[bq*HW + t] = r;
    }
    __syncthreads();
    if (t < WAY*HW) {
        int i = t/HW, y = t%HW;
        int y4 = y >> 2, j = y & 3;
        float s = 0.f;
        #pragma unroll
        for (int m = 0; m < 32; m++) s += redA[i*4 + j][y4 + 9*m];
        ch1s[i][y] = s*rn2s[y];
    }
    // pass2: mw2 (Q rows L1-resident)
    for (int c = t; c < CCH; c += 288) {
        const float4* row = Q4 + c*9;
        float a = 0.f;
        #pragma unroll
        for (int y4 = 0; y4 < 9; y4++) {
            float4 v = row[y4];
            a += v.x*rn2s[y4*4] + v.y*rn2s[y4*4+1] + v.z*rn2s[y4*4+2] + v.w*rn2s[y4*4+3];
        }
        g_mw2[bq*CCH + c] = a*(1.f/36.f);
    }
    __syncthreads();
    if (t < WAY*MID) {  // path1 conv1
        int i = t/MID, m = t%MID;
        float a = b1[m];
        #pragma unroll
        for (int y = 0; y < HW; y++) a += w1[m*HW + y]*ch1s[i][y];
        int p = (b*WAY + i)*NQ + q;
        g_yv[p*MID + m] = a;
        atomicAdd(&g_stats[m], a); atomicAdd(&g_stats[MID + m], a*a);
    }
}

// path2 conv input + conv1 + BN stats; per (bi, q-chunk16); smem-tiled P (c-chunk 64)
// LDS.128 for mw2; staging loop strength-reduced (288 = 8*36)
__global__ void __launch_bounds__(288) k_ch2f(const float* __restrict__ w1,
                                              const float* __restrict__ b1) {
    int bi = blockIdx.x; int qc = blockIdx.y*16;
    int b = bi/WAY;
    const float* P = g_protos + (size_t)bi*CHW;
    __shared__ float mw2s[16*CCH];   // 32KB
    __shared__ float tile[64*37];    // 9.47KB
    __shared__ float ch2s[16][HW];
    __shared__ float rn1s[HW];
    int t = threadIdx.x;
    if (t < HW) rn1s[t] = g_rn1[bi*HW + t];
    {
        float4* dst = (float4*)mw2s;
        const float4* src = (const float4*)g_mw2;
        for (int i4 = t; i4 < 16*128; i4 += 288) {
            int ql = i4 >> 7; int qq = qc + ql;
            dst[i4] = (qq < NQ) ? src[(size_t)(b*NQ + qq)*128 + (i4 & 127)]
                                : make_float4(0.f,0.f,0.f,0.f);
        }
    }
    __syncthreads();
    int q0 = t/36, x0 = t%36;          // thread owns (q0,x0) and (q0+8,x0)
    int q1 = q0 + 8;
    float acc0 = 0.f, acc1 = 0.f;
    for (int c0 = 0; c0 < CCH; c0 += 64) {
        #pragma unroll
        for (int k = 0; k < 8; k++) {      // r = q0 + 8k, xx = x0 (288 = 8*36)
            int r = q0 + 8*k;
            tile[r*37 + x0] = P[(c0 + r)*HW + x0];
        }
        __syncthreads();
        const float4* m0p = (const float4*)(mw2s + q0*CCH + c0);
        const float4* m1p = (const float4*)(mw2s + q1*CCH + c0);
        #pragma unroll 4
        for (int c4 = 0; c4 < 16; c4++) {
            float4 m0 = m0p[c4];
            float4 m1 = m1p[c4];
            float p0 = tile[(c4*4+0)*37 + x0];
            float p1 = tile[(c4*4+1)*37 + x0];
            float p2 = tile[(c4*4+2)*37 + x0];
            float p3 = tile[(c4*4+3)*37 + x0];
            acc0 += m0.x*p0; acc0 += m0.y*p1; acc0 += m0.z*p2; acc0 += m0.w*p3;
            acc1 += m1.x*p0; acc1 += m1.y*p1; acc1 += m1.z*p2; acc1 += m1.w*p3;
        }
        __syncthreads();
    }
    ch2s[q0][x0] = acc0*rn1s[x0];
    ch2s[q1][x0] = acc1*rn1s[x0];
    __syncthreads();
    if (t < 16*MID) {
        int g2 = t/MID, m = t%MID; int q2 = qc + g2;
        if (q2 < NQ) {
            float s = b1[m];
            #pragma unroll
            for (int xx = 0; xx < HW; xx++) s += w1[m*HW + xx]*ch2s[g2][xx];
            int p = bi*NQ + q2;
            g_yv[PAIRS*MID + p*MID + m] = s;
            atomicAdd(&g_stats[12 + m], s); atomicAdd(&g_stats[18 + m], s*s);
        }
    }
}

// fused BN-finalize + conv2 (aw) + v2 matvec; per (bi, q-chunk25); c-chunk 64
__global__ void __launch_bounds__(288) k_awv2(const float* __restrict__ gam,
                                              const float* __restrict__ bet,
                                              const float* __restrict__ w2,
                                              const float* __restrict__ b2) {
    int bi = blockIdx.x; int qc = blockIdx.y*25;
    int b = bi/WAY;
    int pb = bi*NQ + qc;
    const float* P = g_protos + (size_t)bi*CHW;
    __shared__ float bnps[24];
    __shared__ float hsh[25][12];
    __shared__ float wv2s[25*HW];
    __shared__ float tile[64*37];
    __shared__ float rn1s[HW];
    int t = threadIdx.x;
    int trow = t/36, tx = t%36;
    if (t < 12) {
        int path = t/MID, m = t%MID;
        float sum = g_stats[path*12 + m];
        float sqs = g_stats[path*12 + MID + m];
        float mu  = sum/(float)PAIRS;
        float var = sqs/(float)PAIRS - mu*mu;
        bnps[path*12 + m]       = mu;
        bnps[path*12 + MID + m] = rsqrtf(var + 1e-5f);
    }
    if (t >= 64 && t < 64 + HW) rn1s[t - 64] = g_rn1[bi*HW + (t - 64)];
    __syncthreads();
    for (int idx = t; idx < 300; idx += 288) {   // cover all 25 pairs
        int pl = idx/12, tt = idx%12, path = tt/MID, m = tt%MID;
        int p = pb + pl;
        float v = g_yv[path*PAIRS*MID + p*MID + m];
        float z = gam[m]*(v - bnps[path*12 + m])*bnps[path*12 + MID + m] + bet[m];
        hsh[pl][tt] = fmaxf(z, 0.f);
    }
    __syncthreads();
    for (int idx = t; idx < 25*72; idx += 288) {
        int pl = idx/72, tt = idx%72, path = tt/HW, k = tt%HW;
        int p = pb + pl; int bq = b*NQ + qc + pl;
        float a = b2[k];
        #pragma unroll
        for (int m = 0; m < MID; m++) a += w2[k*MID + m]*hsh[pl][path*MID + m];
        if (path == 0) g_wv1[p*HW + k] = a * g_rn2[bq*HW + k];
        else           wv2s[pl*HW + k] = a * rn1s[k];
    }
    __syncthreads();
    // v2[p,c] = sum_x P[c,x]*wv2[p,x]
    for (int c0 = 0; c0 < CCH; c0 += 64) {
        #pragma unroll
        for (int k = 0; k < 8; k++) {
            int r = trow + 8*k;
            tile[r*37 + tx] = P[(c0 + r)*HW + tx];
        }
        __syncthreads();
        #pragma unroll
        for (int r = 0; r < 6; r++) {
            int item = t + 288*r;
            if (item < 1600) {
                int q = item >> 6, c_l = item & 63;
                float a = 0.f;
                #pragma unroll
                for (int xx = 0; xx < HW; xx++) a += tile[c_l*37 + xx]*wv2s[q*HW + xx];
                g_v2[(size_t)(pb + q)*CCH + c0 + c_l] = a;
            }
        }
        __syncthreads();
    }
}

// fused v1 + s2 + attsel; per bq, smem-tiled Q pass (c-chunk 64)
__global__ void __launch_bounds__(288) k_v1s2(const float* __restrict__ Q,
                                              const float* __restrict__ qt) {
    int bq = blockIdx.x; int b = bq/NQ, q = bq%NQ;
    int t = threadIdx.x;
    __shared__ float v2s[WAY*CCH];
    __shared__ float wv1s[WAY][HW];
    __shared__ float tile[64*37];
    __shared__ float rn2s[HW];
    __shared__ float s2s[WAY][HW];
    __shared__ float mx[WAY], sm[WAY], qts[WAY];
    {
        float4* dst = (float4*)v2s;
        for (int i4 = t; i4 < WAY*CCH/4; i4 += 288) {
            int i = i4/(CCH/4);
            const float4* src = (const float4*)(g_v2 + (size_t)((b*WAY + i)*NQ + q)*CCH);
            dst[i4] = src[i4 - i*(CCH/4)];
        }
    }
    if (t < WAY*HW) wv1s[t/HW][t%HW] = g_wv1[((b*WAY + t/HW)*NQ + q)*HW + t%HW];
    if (t < HW) rn2s[t] = g_rn2[bq*HW + t];
    if (t < WAY) qts[t] = qt[(size_t)bq*WAY + t];
    __syncthreads();
    const float* Qb = Q + (size_t)bq*CHW;
    int trow = t/36, tx = t%36;
    int si = (t < 180) ? t/36 : 0;
    int sx = t%36;
    float s2a = 0.f;
    for (int c0 = 0; c0 < CCH; c0 += 64) {
        #pragma unroll
        for (int k = 0; k < 8; k++) {
            int r = trow + 8*k;
            tile[r*37 + tx] = Qb[(c0 + r)*HW + tx];
        }
        __syncthreads();
        #pragma unroll
        for (int r = 0; r < 2; r++) {
            int item = t + 288*r;
            if (item < 320) {
                int i = item >> 6, c_l = item & 63;
                float a = 0.f;
                #pragma unroll
                for (int y = 0; y < HW; y++) a += tile[c_l*37 + y]*wv1s[i][y];
                g_v1[(size_t)((b*WAY + i)*NQ + q)*CCH + c0 + c_l] = a;
            }
        }
        if (t < 180) {
            #pragma unroll 8
            for (int c = 0; c < 64; c++) s2a += v2s[si*CCH + c0 + c]*tile[c*37 + sx];
        }
        __syncthreads();
    }
    if (t < 180) s2s[si][sx] = s2a * rn2s[sx] * (1.f/36.f);
    __syncthreads();
    if (t < WAY) {
        float m = -1e30f;
        #pragma unroll
        for (int yy = 0; yy < HW; yy++) m = fmaxf(m, s2s[t][yy]);
        mx[t] = m;
    }
    __syncthreads();
    if (t < 180) s2s[si][sx] = expf((s2s[si][sx] - mx[si])*40.f);
    __syncthreads();
    if (t < WAY) {
        float s = 0.f;
        #pragma unroll
        for (int yy = 0; yy < HW; yy++) s += s2s[t][yy];
        sm[t] = s;
    }
    __syncthreads();
    if (t < HW) {
        float a = 0.f;
        #pragma unroll
        for (int i = 0; i < WAY; i++) a += (s2s[i][t]/sm[i] + 1.f)*qts[i];
        g_asel[bq*HW + t] = a;
    }
}

// fused s1 + softmax + proto-pool + l2norm; per (bi, q-chunk16)
__global__ void __launch_bounds__(288) k_s1pool() {
    int bi = blockIdx.x; int qc = blockIdx.y*16;
    const float* P = g_protos + (size_t)bi*CHW;
    __shared__ float v1s[16*CCH];
    __shared__ float tile[64*37];
    __shared__ float att[16][HW];
    __shared__ float rn1s[HW];
    __shared__ float mx[16], sm[16];
    __shared__ float pnfs[16];
    int t = threadIdx.x;
    if (t < HW) rn1s[t] = g_rn1[bi*HW + t];
    {
        float4* dst = (float4*)v1s;
        const float4* src = (const float4*)g_v1;
        for (int i4 = t; i4 < 16*CCH/4; i4 += 288) {
            int ql = i4 >> 7;
            int qq = qc + ql;
            dst[i4] = (qq < NQ) ? src[(size_t)(bi*NQ + qq)*(CCH/4) + (i4 & 127)]
                                : make_float4(0.f,0.f,0.f,0.f);
        }
    }
    __syncthreads();
    int x = t%36, trow = t/36;
    float acc0 = 0.f, acc1 = 0.f;
    for (int c0 = 0; c0 < CCH; c0 += 64) {
        #pragma unroll
        for (int k = 0; k < 8; k++) {
            int r = trow + 8*k;
            tile[r*37 + x] = P[(c0 + r)*HW + x];
        }
        __syncthreads();
        #pragma unroll 8
        for (int c = 0; c < 64; c++) {
            float pv = tile[c*37 + x];
            acc0 += v1s[trow*CCH + c0 + c]*pv;
            acc1 += v1s[(trow+8)*CCH + c0 + c]*pv;
        }
        __syncthreads();
    }
    att[trow][x]   = acc0*rn1s[x]*(1.f/36.f);
    att[trow+8][x] = acc1*rn1s[x]*(1.f/36.f);
    __syncthreads();
    if (t < 16) {
        float m = -1e30f;
        #pragma unroll
        for (int xx = 0; xx < HW; xx++) m = fmaxf(m, att[t][xx]);
        mx[t] = m;
    }
    __syncthreads();
    att[trow][x]   = expf((att[trow][x]   - mx[trow])*40.f);
    att[trow+8][x] = expf((att[trow+8][x] - mx[trow+8])*40.f);
    __syncthreads();
    if (t < 16) {
        float s = 0.f;
        #pragma unroll
        for (int xx = 0; xx < HW; xx++) s += att[t][xx];
        sm[t] = s;
    }
    __syncthreads();
    att[trow][x]   = att[trow][x]/sm[trow]     + 1.f;
    att[trow+8][x] = att[trow+8][x]/sm[trow+8] + 1.f;
    __syncthreads();
    // pool phase (c-chunk 32, uses first 32 rows of tile)
    int q_a = t >> 5, c_l = t & 31;
    int q_b = q_a + 9;
    float ssq_a = 0.f, ssq_b = 0.f;
    for (int c0 = 0; c0 < CCH; c0 += 32) {
        #pragma unroll
        for (int j = 0; j < 4; j++)
            tile[(trow + 8*j)*37 + x] = P[(c0 + trow + 8*j)*HW + x];
        __syncthreads();
        {
            float a = 0.f;
            #pragma unroll
            for (int xx = 0; xx < HW; xx++) a += tile[c_l*37 + xx]*att[q_a][xx];
            a *= (1.f/36.f);
            v1s[q_a*CCH + c0 + c_l] = a;
            ssq_a += a*a;
        }
        if (q_b < 16) {
            float a = 0.f;
            #pragma unroll
            for (int xx = 0; xx < HW; xx++) a += tile[c_l*37 + xx]*att[q_b][xx];
            a *= (1.f/36.f);
            v1s[q_b*CCH + c0 + c_l] = a;
            ssq_b += a*a;
        }
        __syncthreads();
    }
    #pragma unroll
    for (int off = 16; off > 0; off >>= 1) {
        ssq_a += __shfl_xor_sync(0xffffffffu, ssq_a, off);
        ssq_b += __shfl_xor_sync(0xffffffffu, ssq_b, off);
    }
    int lane = t & 31, warp = t >> 5;
    if (lane == 0) {
        pnfs[warp] = 1.f/fmaxf(sqrtf(ssq_a), 1e-12f);
        if (warp < 7) pnfs[warp + 9] = 1.f/fmaxf(sqrtf(ssq_b), 1e-12f);
    }
    __syncthreads();
    for (int idx = t; idx < 16*CCH; idx += 288) {
        int ql = idx >> 9; int qq = qc + ql;
        if (qq < NQ) g_v1[(size_t)(bi*NQ + qq)*CCH + (idx & 511)] = v1s[idx]*pnfs[ql];
    }
}

// logits GEMM + fused cls_scores
__global__ void __launch_bounds__(128) k_logit(const float* __restrict__ Q,
                                               const float* __restrict__ cw,
                                               const float* __restrict__ cb,
                                               float* __restrict__ out1,
                                               float* __restrict__ out2) {
    int n0 = blockIdx.x*64;
    int t = threadIdx.x;
    int tn = t & 15, tm = t >> 4;
    __shared__ float shAB[2240];
    __shared__ float pools[3*WAY*CCH];
    int bq0 = n0/36;
    {
        float4* dst = (float4*)pools;
        const float4* src = (const float4*)g_v1;
        for (int i4 = t; i4 < 3*WAY*(CCH/4); i4 += 128) {
            int r = i4/640; int rem = i4 - r*640; int i = rem >> 7; int c4 = rem & 127;
            int bq = bq0 + r;
            float4 v = make_float4(0.f,0.f,0.f,0.f);
            if (bq < BB*NQ) {
                int b = bq/NQ, q = bq%NQ;
                v = src[(size_t)((b*WAY + i)*NQ + q)*(CCH/4) + c4];
            }
            dst[i4] = v;
        }
    }
    int nn_l = t & 63, kgrp = t >> 6;
    int nglob = n0 + nn_l;
    bool nval = nglob < NTOT;
    int bq_l = nval ? nglob/36 : 0;
    int x_l  = nval ? nglob%36 : 0;
    const float* qbase = Q + (size_t)bq_l*CHW + x_l;
    int o_a = t >> 1, ka = (t & 1)*8;
    float acc[8][4];
    float accc[4][WAY];
    #pragma unroll
    for (int r = 0; r < 8; r++)
        #pragma unroll
        for (int j = 0; j < 4; j++) acc[r][j] = 0.f;
    #pragma unroll
    for (int j = 0; j < 4; j++)
        #pragma unroll
        for (int i = 0; i < WAY; i++) accc[j][i] = 0.f;
    int rj[4];
    #pragma unroll
    for (int j = 0; j < 4; j++) {
        int n = n0 + tn*4 + j;
        rj[j] = (n < NTOT) ? (n/36 - bq0) : 0;
    }
    for (int k0 = 0; k0 < CCH; k0 += 16) {
        float4 av0 = *(const float4*)(cw + o_a*CCH + k0 + ka);
        float4 av1 = *(const float4*)(cw + o_a*CCH + k0 + ka + 4);
        shAB[(ka+0)*72 + o_a] = av0.x; shAB[(ka+1)*72 + o_a] = av0.y;
        shAB[(ka+2)*72 + o_a] = av0.z; shAB[(ka+3)*72 + o_a] = av0.w;
        shAB[(ka+4)*72 + o_a] = av1.x; shAB[(ka+5)*72 + o_a] = av1.y;
        shAB[(ka+6)*72 + o_a] = av1.z; shAB[(ka+7)*72 + o_a] = av1.w;
        #pragma unroll
        for (int j = 0; j < 8; j++) {
            int kk = kgrp*8 + j;
            shAB[1152 + kk*68 + nn_l] = nval ? qbase[(size_t)(k0 + kk)*HW] : 0.f;
        }
        __syncthreads();
        #pragma unroll
        for (int k = 0; k < 16; k++) {
            float4 af0 = *(const float4*)&shAB[k*72 + tm*8];
            float4 af1 = *(const float4*)&shAB[k*72 + tm*8 + 4];
            float4 bf  = *(const float4*)&shAB[1152 + k*68 + tn*4];
            float am[8] = {af0.x,af0.y,af0.z,af0.w,af1.x,af1.y,af1.z,af1.w};
            float bn[4] = {bf.x,bf.y,bf.z,bf.w};
            #pragma unroll
            for (int r = 0; r < 8; r++)
                #pragma unroll
                for (int j = 0; j < 4; j++) acc[r][j] += am[r]*bn[j];
        }
        #pragma unroll
        for (int kk2 = 0; kk2 < 2; kk2++) {
            int kk = tm*2 + kk2;
            #pragma unroll
            for (int j = 0; j < 4; j++) {
                float bn = shAB[1152 + kk*68 + tn*4 + j];
                #pragma unroll
                for (int i = 0; i < WAY; i++)
                    accc[j][i] += pools[rj[j]*WAY*CCH + i*CCH + k0 + kk]*bn;
            }
        }
        __syncthreads();
    }
    #pragma unroll
    for (int j = 0; j < 4; j++) {
        int n = n0 + tn*4 + j;
        if (n >= NTOT) continue;
        int bq = n/36, x = n%36;
        float av = g_asel[n];
        #pragma unroll
        for (int r = 0; r < 8; r++) {
            int o = tm*8 + r;
            out1[((size_t)bq*NCLS + o)*HW + x] = acc[r][j]*av + cb[o];
        }
    }
    #pragma unroll
    for (int j = 0; j < 4; j++)
        #pragma unroll
        for (int i = 0; i < WAY; i++)
            accc[j][i] += __shfl_xor_sync(0xffffffffu, accc[j][i], 16);
    if ((tm & 1) == 0) {
        int g = tm >> 1;
        #pragma unroll
        for (int j = 0; j < 4; j++)
            #pragma unroll
            for (int i = 0; i < WAY; i++)
                shAB[g*320 + (tn*4 + j)*WAY + i] = accc[j][i];
    }
    __syncthreads();
    for (int idx = t; idx < 320; idx += 128) {
        int n_l = idx/WAY, i = idx%WAY;
        int n = n0 + n_l;
        if (n < NTOT) {
            float s = shAB[idx] + shAB[320 + idx] + shAB[640 + idx] + shAB[960 + idx];
            int bq = n/36, x = n%36;
            out2[((size_t)bq*WAY + i)*HW + x] = 7.f * g_rn2[n] * s;
        }
    }
}

// ---------------- launch ----------------
extern "C" void kernel_launch(void* const* d_in, const int* in_sizes, int n_in,
                              void* d_out, int out_size) {
    (void)in_sizes; (void)n_in; (void)out_size;
    const float* support = (const float*)d_in[0];
    const float* query   = (const float*)d_in[1];
    const float* st      = (const float*)d_in[2];
    const float* qt      = (const float*)d_in[3];
    const float* w1      = (const float*)d_in[4];
    const float* b1      = (const float*)d_in[5];
    const float* gam     = (const float*)d_in[6];
    const float* bet     = (const float*)d_in[7];
    const float* w2      = (const float*)d_in[8];
    const float* b2      = (const float*)d_in[9];
    const float* cw      = (const float*)d_in[10];
    const float* cb      = (const float*)d_in[11];
    float* out1 = (float*)d_out;                               // logits 600*64*36
    float* out2 = out1 + (size_t)BB*NQ*NCLS*HW;                // cls_scores 600*5*36

    k_protos   <<<dim3(16, BB), 288>>>(support, st);
    k_prep1    <<<BB*WAY, 288>>>();
    k_prep2ch1 <<<BB*NQ, 288>>>(query, w1, b1);
    k_ch2f     <<<dim3(BB*WAY, 5), 288>>>(w1, b1);
    k_awv2     <<<dim3(BB*WAY, 3), 288>>>(gam, bet, w2, b2);
    k_v1s2     <<<BB*NQ, 288>>>(query, qt);
    k_s1pool   <<<dim3(BB*WAY, 5), 288>>>();
    k_logit    <<<(NTOT + 63)/64, 128>>>(query, cw, cb, out1, out2);
}